// round 5
// baseline (speedup 1.0000x reference)
#include <cuda_runtime.h>

#define BB 8
#define SS 2048
#define DD 1024
#define LRATE 0.01f

typedef unsigned long long u64;

// Scratch for projected views K, V, Q: [B*S, D] each (64MB each).
__device__ float g_K[BB * SS * DD];
__device__ float g_V[BB * SS * DD];
__device__ float g_Q[BB * SS * DD];

// ---------------- packed f32x2 helpers (FFMA2: 2 MACs/instr) ----------------
__device__ __forceinline__ u64 pk2(float x, float y) {
    u64 r; asm("mov.b64 %0, {%1, %2};" : "=l"(r) : "f"(x), "f"(y)); return r;
}
__device__ __forceinline__ float2 upk2(u64 v) {
    float2 r; asm("mov.b64 {%0, %1}, %2;" : "=f"(r.x), "=f"(r.y) : "l"(v)); return r;
}
__device__ __forceinline__ u64 f2fma(u64 a, u64 b, u64 c) {
    u64 d; asm("fma.rn.f32x2 %0, %1, %2, %3;" : "=l"(d) : "l"(a), "l"(b), "l"(c)); return d;
}
__device__ __forceinline__ float warpsum(float v) {
#pragma unroll
    for (int o = 16; o > 0; o >>= 1) v += __shfl_xor_sync(0xffffffffu, v, o);
    return v;
}

// ======================= Projection GEMM =======================
// C[m][n] = sum_k A[m][k] * Th[n][k]   (both K-major "NT" GEMM)
// M = B*S = 16384, N = 1024, K = 1024.  blockIdx.z selects view.
#define GBM 128
#define GBN 128
#define GBK 16
#define GPAD 132              // pad: 16B-aligned rows + only 2-way STS conflict
#define KITERS (DD / GBK)     // 64

__global__ void __launch_bounds__(256, 1) proj_kernel(
    const float* __restrict__ A,
    const float* __restrict__ T0,
    const float* __restrict__ T1,
    const float* __restrict__ T2)
{
    __shared__ __align__(16) float As[GBK][GPAD];
    __shared__ __align__(16) float Bs[GBK][GPAD];

    const float* Th = (blockIdx.z == 0) ? T0 : ((blockIdx.z == 1) ? T1 : T2);
    float* C = (blockIdx.z == 0) ? g_K : ((blockIdx.z == 1) ? g_V : g_Q);

    const int m0 = blockIdx.x * GBM;
    const int n0 = blockIdx.y * GBN;
    const int tid = threadIdx.x;
    const int tx = tid & 15, ty = tid >> 4;

    u64 acc[8][4];
#pragma unroll
    for (int i = 0; i < 8; i++)
#pragma unroll
        for (int p = 0; p < 4; p++) acc[i][p] = 0ull;

    const int r0 = tid >> 2;       // 0..63
    const int kq = tid & 3;        // 0..3 (which float4 of the 16-wide k tile)

    // prefetch tile 0
    float4 ra0 = *(const float4*)&A [(m0 + r0)      * DD + 4 * kq];
    float4 ra1 = *(const float4*)&A [(m0 + r0 + 64) * DD + 4 * kq];
    float4 rb0 = *(const float4*)&Th[(n0 + r0)      * DD + 4 * kq];
    float4 rb1 = *(const float4*)&Th[(n0 + r0 + 64) * DD + 4 * kq];

    for (int kt = 0; kt < KITERS; kt++) {
        // store tiles transposed: As[k][m], Bs[k][n]
        As[4 * kq + 0][r0] = ra0.x; As[4 * kq + 1][r0] = ra0.y;
        As[4 * kq + 2][r0] = ra0.z; As[4 * kq + 3][r0] = ra0.w;
        As[4 * kq + 0][r0 + 64] = ra1.x; As[4 * kq + 1][r0 + 64] = ra1.y;
        As[4 * kq + 2][r0 + 64] = ra1.z; As[4 * kq + 3][r0 + 64] = ra1.w;
        Bs[4 * kq + 0][r0] = rb0.x; Bs[4 * kq + 1][r0] = rb0.y;
        Bs[4 * kq + 2][r0] = rb0.z; Bs[4 * kq + 3][r0] = rb0.w;
        Bs[4 * kq + 0][r0 + 64] = rb1.x; Bs[4 * kq + 1][r0 + 64] = rb1.y;
        Bs[4 * kq + 2][r0 + 64] = rb1.z; Bs[4 * kq + 3][r0 + 64] = rb1.w;
        __syncthreads();

        if (kt + 1 < KITERS) {
            const int kb = (kt + 1) * GBK + 4 * kq;
            ra0 = *(const float4*)&A [(m0 + r0)      * DD + kb];
            ra1 = *(const float4*)&A [(m0 + r0 + 64) * DD + kb];
            rb0 = *(const float4*)&Th[(n0 + r0)      * DD + kb];
            rb1 = *(const float4*)&Th[(n0 + r0 + 64) * DD + kb];
        }

#pragma unroll
        for (int kk = 0; kk < GBK; kk++) {
            const float4 a0 = *(const float4*)&As[kk][ty * 8];
            const float4 a1 = *(const float4*)&As[kk][ty * 8 + 4];
            const ulonglong2 b01 = *(const ulonglong2*)&Bs[kk][tx * 8];
            const ulonglong2 b23 = *(const ulonglong2*)&Bs[kk][tx * 8 + 4];
            u64 bp[4] = {b01.x, b01.y, b23.x, b23.y};
            const float av[8] = {a0.x, a0.y, a0.z, a0.w, a1.x, a1.y, a1.z, a1.w};
#pragma unroll
            for (int i = 0; i < 8; i++) {
                const u64 ap = pk2(av[i], av[i]);
#pragma unroll
                for (int p = 0; p < 4; p++) acc[i][p] = f2fma(ap, bp[p], acc[i][p]);
            }
        }
        __syncthreads();
    }

#pragma unroll
    for (int i = 0; i < 8; i++) {
        const int m = m0 + ty * 8 + i;
        const float2 q0 = upk2(acc[i][0]), q1 = upk2(acc[i][1]);
        const float2 q2 = upk2(acc[i][2]), q3 = upk2(acc[i][3]);
        *(float4*)&C[m * DD + n0 + tx * 8]     = make_float4(q0.x, q0.y, q1.x, q1.y);
        *(float4*)&C[m * DD + n0 + tx * 8 + 4] = make_float4(q2.x, q2.y, q3.x, q3.y);
    }
}

// ======================= Persistent TTT scan =======================
// Grid (16 row-chunks, 8 batches) = 128 blocks, single wave.
// Each block owns 64 rows of W: warp w owns rows base+4w..base+4w+3;
// first 3 rows in SMEM (48 rows -> 192KB), 4th row in registers.
#define NWARP 16
#define SMEM_ROWS 48
#define SCAN_SMEM (SMEM_ROWS * DD * 4)

__global__ void __launch_bounds__(512, 1) scan_kernel(
    const float* __restrict__ W0,
    const float* __restrict__ b0,
    float* __restrict__ out)
{
    extern __shared__ __align__(16) float Wsh[];
    ulonglong2* Wsh2 = (ulonglong2*)Wsh;

    const int tid = threadIdx.x;
    const int w = tid >> 5;
    const int lane = tid & 31;
    const int batch = blockIdx.y;
    const int row0 = blockIdx.x * 64;

    // ---- init W slice ----
    {
        const float4* W04 = (const float4*)W0;
        float4* Wsh4 = (float4*)Wsh;
        for (int i = tid; i < SMEM_ROWS * 256; i += 512) {
            const int s = i >> 8;          // smem row slot 0..47
            const int c = i & 255;         // float4 column
            const int grow = row0 + (s / 3) * 4 + (s % 3);
            Wsh4[i] = W04[grow * 256 + c];
        }
    }
    ulonglong2 wr[8];                       // register row = row0 + 4w + 3
    {
        const ulonglong2* W02 = (const ulonglong2*)W0;
        const int gr3 = row0 + 4 * w + 3;
#pragma unroll
        for (int j = 0; j < 8; j++) wr[j] = W02[gr3 * 256 + lane + 32 * j];
    }
    float bv[4];
#pragma unroll
    for (int i = 0; i < 4; i++) bv[i] = b0[row0 + 4 * w + i];
    __syncthreads();

    const float* Kb = g_K + batch * SS * DD;
    const float* Vb = g_V + batch * SS * DD;
    const float* Qb = g_Q + batch * SS * DD;
    float* Ob = out + (size_t)batch * SS * DD;

    const float cdh = 2.0f / (float)DD;
    const int s0 = (3 * w + 0) * 256 + lane;
    const int s1 = (3 * w + 1) * 256 + lane;
    const int s2 = (3 * w + 2) * 256 + lane;

    for (int t = 0; t < SS; t++) {
        const ulonglong2* kt = (const ulonglong2*)(Kb + t * DD);
        const ulonglong2* qt = (const ulonglong2*)(Qb + t * DD);

        // ---- pass A: dk = W_old @ k ----
        ulonglong2 kf[8];
        u64 dk0 = 0, dk1 = 0, dk2a = 0, dk3 = 0;
#pragma unroll
        for (int j = 0; j < 8; j++) {
            kf[j] = __ldg(kt + lane + 32 * j);
            const ulonglong2 w0v = Wsh2[s0 + 32 * j];
            const ulonglong2 w1v = Wsh2[s1 + 32 * j];
            const ulonglong2 w2v = Wsh2[s2 + 32 * j];
            dk0 = f2fma(w0v.x, kf[j].x, dk0); dk0 = f2fma(w0v.y, kf[j].y, dk0);
            dk1 = f2fma(w1v.x, kf[j].x, dk1); dk1 = f2fma(w1v.y, kf[j].y, dk1);
            dk2a = f2fma(w2v.x, kf[j].x, dk2a); dk2a = f2fma(w2v.y, kf[j].y, dk2a);
            dk3 = f2fma(wr[j].x, kf[j].x, dk3); dk3 = f2fma(wr[j].y, kf[j].y, dk3);
        }

        u64 dkp[4] = {dk0, dk1, dk2a, dk3};
        u64 ng[4];
        float g[4];
#pragma unroll
        for (int r = 0; r < 4; r++) {
            const float2 p = upk2(dkp[r]);
            const float dot = warpsum(p.x + p.y);
            const float pred = dot + bv[r];
            const float vv = __ldg(Vb + t * DD + row0 + 4 * w + r);
            g[r] = cdh * (pred - vv);
            bv[r] -= LRATE * g[r];
            const float m = -LRATE * g[r];
            ng[r] = pk2(m, m);
        }

        // ---- pass B: W -= LR*g*k^T fused with dq = W_new @ q ----
        u64 dq0 = 0, dq1 = 0, dq2a = 0, dq3 = 0;
#pragma unroll
        for (int j = 0; j < 8; j++) {
            const ulonglong2 q4 = __ldg(qt + lane + 32 * j);

            ulonglong2 w0v = Wsh2[s0 + 32 * j];
            w0v.x = f2fma(ng[0], kf[j].x, w0v.x);
            w0v.y = f2fma(ng[0], kf[j].y, w0v.y);
            Wsh2[s0 + 32 * j] = w0v;
            dq0 = f2fma(w0v.x, q4.x, dq0); dq0 = f2fma(w0v.y, q4.y, dq0);

            ulonglong2 w1v = Wsh2[s1 + 32 * j];
            w1v.x = f2fma(ng[1], kf[j].x, w1v.x);
            w1v.y = f2fma(ng[1], kf[j].y, w1v.y);
            Wsh2[s1 + 32 * j] = w1v;
            dq1 = f2fma(w1v.x, q4.x, dq1); dq1 = f2fma(w1v.y, q4.y, dq1);

            ulonglong2 w2v = Wsh2[s2 + 32 * j];
            w2v.x = f2fma(ng[2], kf[j].x, w2v.x);
            w2v.y = f2fma(ng[2], kf[j].y, w2v.y);
            Wsh2[s2 + 32 * j] = w2v;
            dq2a = f2fma(w2v.x, q4.x, dq2a); dq2a = f2fma(w2v.y, q4.y, dq2a);

            wr[j].x = f2fma(ng[3], kf[j].x, wr[j].x);
            wr[j].y = f2fma(ng[3], kf[j].y, wr[j].y);
            dq3 = f2fma(wr[j].x, q4.x, dq3); dq3 = f2fma(wr[j].y, q4.y, dq3);
        }

        u64 dqp[4] = {dq0, dq1, dq2a, dq3};
#pragma unroll
        for (int r = 0; r < 4; r++) {
            const float2 p = upk2(dqp[r]);
            const float dot = warpsum(p.x + p.y);
            const float ov = dot + bv[r];
            if (lane == 0) Ob[t * DD + row0 + 4 * w + r] = ov;
        }
    }
}

// ======================= launch =======================
extern "C" void kernel_launch(void* const* d_in, const int* in_sizes, int n_in,
                              void* d_out, int out_size)
{
    const float* in_seq = (const float*)d_in[0];
    const float* thK    = (const float*)d_in[1];
    const float* thV    = (const float*)d_in[2];
    const float* thQ    = (const float*)d_in[3];
    const float* W0     = (const float*)d_in[4];
    const float* b0     = (const float*)d_in[5];
    float* out = (float*)d_out;

    cudaFuncSetAttribute(scan_kernel, cudaFuncAttributeMaxDynamicSharedMemorySize, SCAN_SMEM);

    dim3 gproj((BB * SS) / GBM, DD / GBN, 3);   // 128 x 8 x 3
    proj_kernel<<<gproj, 256>>>(in_seq, thK, thV, thQ);

    dim3 gscan(DD / 64, BB);                    // 16 x 8 = 128 persistent blocks
    scan_kernel<<<gscan, 512, SCAN_SMEM>>>(W0, b0, out);
}